// round 10
// baseline (speedup 1.0000x reference)
#include <cuda_runtime.h>

#define N_NODES 100000
#define E_EDGES 1200000
#define F 64

#define SCAN_BLK 256
#define NPART ((N_NODES + SCAN_BLK - 1) / SCAN_BLK)   // 391
#define WSTRIDE 66
#define ASTRIDE 65

// ---------------- scratch (device globals; no allocation allowed) ----------
__device__ int   g_is64;
__device__ int   g_cnt[N_NODES];
__device__ int   g_cur[N_NODES];
__device__ int   g_off[N_NODES + 1];
__device__ int   g_part[NPART];
__device__ int   g_pscan[NPART];
__device__ int   g_srcs[E_EDGES];
__device__ __align__(16) float g_agg[N_NODES * F];
__device__ __align__(16) float g_pre[N_NODES * F];
__device__ __align__(16) float g_hbuf[2][N_NODES * F];

// ---------------- FFMA2 helpers ----------------------------------------------
__device__ __forceinline__ unsigned long long pack2(float v) {
    unsigned long long r;
    asm("mov.b64 %0, {%1, %1};" : "=l"(r) : "f"(v));
    return r;
}
__device__ __forceinline__ void ffma2(unsigned long long& acc, unsigned long long a,
                                      unsigned long long b) {
    asm("fma.rn.f32x2 %0, %1, %2, %0;" : "+l"(acc) : "l"(a), "l"(b));
}
__device__ __forceinline__ float2 unpack2(unsigned long long v) {
    float lo, hi;
    asm("mov.b64 {%0, %1}, %2;" : "=f"(lo), "=f"(hi) : "l"(v));
    return make_float2(lo, hi);
}

// ---------------- zero + dtype detection (merged) ---------------------------
__global__ void zerodetect_kernel(const int* __restrict__ ei32) {
    int i = blockIdx.x * blockDim.x + threadIdx.x;
    if (i < N_NODES) { g_cnt[i] = 0; g_cur[i] = 0; }
    if (blockIdx.x == 0) {
        __shared__ int any;
        if (threadIdx.x == 0) any = 0;
        __syncthreads();
        int acc = 0;
        for (int j = threadIdx.x * 2 + 1; j < 4096; j += 2 * blockDim.x)
            acc |= ei32[j];
        if (acc) atomicOr(&any, 1);
        __syncthreads();
        if (threadIdx.x == 0) g_is64 = (any == 0) ? 1 : 0;
    }
}

__device__ __forceinline__ int load_idx(const void* ei, long long pos, bool is64) {
    if (is64) return (int)((const long long*)ei)[pos];
    return ((const int*)ei)[pos];
}

// ---------------- CSR build -------------------------------------------------
__global__ void count_kernel(const void* __restrict__ ei) {
    const bool is64 = (g_is64 != 0);
    int stride = gridDim.x * blockDim.x;
    for (int e = blockIdx.x * blockDim.x + threadIdx.x; e < E_EDGES; e += stride) {
        int d = load_idx(ei, (long long)E_EDGES + e, is64);
        if ((unsigned)d < (unsigned)N_NODES)
            atomicAdd(&g_cnt[d], 1);
    }
}

__global__ void part_sum_kernel() {
    __shared__ int red[SCAN_BLK];
    int i = blockIdx.x * SCAN_BLK + threadIdx.x;
    red[threadIdx.x] = (i < N_NODES) ? g_cnt[i] : 0;
    __syncthreads();
    for (int s = SCAN_BLK / 2; s > 0; s >>= 1) {
        if (threadIdx.x < s) red[threadIdx.x] += red[threadIdx.x + s];
        __syncthreads();
    }
    if (threadIdx.x == 0) g_part[blockIdx.x] = red[0];
}

__global__ void part_scan_kernel() {
    __shared__ int s[512];
    int t = threadIdx.x;
    int v = (t < NPART) ? g_part[t] : 0;
    s[t] = v;
    __syncthreads();
    for (int off = 1; off < 512; off <<= 1) {
        int u = (t >= off) ? s[t - off] : 0;
        __syncthreads();
        s[t] += u;
        __syncthreads();
    }
    if (t < NPART) g_pscan[t] = s[t] - v;
    if (t == 511) g_off[N_NODES] = s[511];
}

__global__ void offsets_kernel() {
    __shared__ int s[SCAN_BLK];
    int t = threadIdx.x;
    int i = blockIdx.x * SCAN_BLK + t;
    int v = (i < N_NODES) ? g_cnt[i] : 0;
    s[t] = v;
    __syncthreads();
    for (int off = 1; off < SCAN_BLK; off <<= 1) {
        int u = (t >= off) ? s[t - off] : 0;
        __syncthreads();
        s[t] += u;
        __syncthreads();
    }
    if (i < N_NODES) g_off[i] = g_pscan[blockIdx.x] + s[t] - v;
}

__global__ void fill_kernel(const void* __restrict__ ei) {
    const bool is64 = (g_is64 != 0);
    int stride = gridDim.x * blockDim.x;
    for (int e = blockIdx.x * blockDim.x + threadIdx.x; e < E_EDGES; e += stride) {
        int d = load_idx(ei, (long long)E_EDGES + e, is64);
        int s = load_idx(ei, (long long)e, is64);
        if ((unsigned)d < (unsigned)N_NODES && (unsigned)s < (unsigned)N_NODES) {
            int p = g_off[d] + atomicAdd(&g_cur[d], 1);
            g_srcs[p] = s;
        }
    }
}

// ---------------- agg + pre: gather-aggregate AND self x Wr^T ---------------
// One warp per node. The gather is memory-bound with idle FMA slots; the
// pre = h[w] @ Wr^T GEMV (64 FFMA2/lane against smem Wr) fills them.
__global__ void __launch_bounds__(256)
agg_kernel(const float* __restrict__ x, int hin_sel, const float* __restrict__ Wr) {
    __shared__ float wrs[64 * WSTRIDE];      // k-major: wrs[k][f] = Wr[f*64+k]
    const float* __restrict__ h = (hin_sel < 0) ? x : g_hbuf[hin_sel];

    for (int idx = threadIdx.x; idx < 64 * 64; idx += 256) {
        int f = idx >> 6, k = idx & 63;
        wrs[k * WSTRIDE + f] = Wr[idx];
    }
    __syncthreads();

    int w = (blockIdx.x * blockDim.x + threadIdx.x) >> 5;
    int lane = threadIdx.x & 31;
    if (w >= N_NODES) return;

    const int q = lane & 15;        // float4 slot within row
    const int half = lane >> 4;     // 0: even edges, 1: odd edges

    // ---- neighbor sum (edge-pair float4 gather) ----
    float ax = 0.f, ay = 0.f, az = 0.f, aw = 0.f;
    int p = g_off[w], pe = g_off[w + 1];
    while (p < pe) {
        int cnt = pe - p; if (cnt > 32) cnt = 32;
        int idx = (lane < cnt) ? g_srcs[p + lane] : 0;
        int j = 0;
        for (; j + 4 <= cnt; j += 4) {
            int s0 = __shfl_sync(0xffffffffu, idx, j + half);
            int s1 = __shfl_sync(0xffffffffu, idx, j + 2 + half);
            float4 v0 = ((const float4*)(h + (size_t)s0 * 64))[q];
            float4 v1 = ((const float4*)(h + (size_t)s1 * 64))[q];
            ax += v0.x + v1.x; ay += v0.y + v1.y;
            az += v0.z + v1.z; aw += v0.w + v1.w;
        }
        for (; j < cnt; j += 2) {
            int e = j + half;
            int s0 = __shfl_sync(0xffffffffu, idx, e & 31);
            if (e < cnt) {
                float4 v = ((const float4*)(h + (size_t)s0 * 64))[q];
                ax += v.x; ay += v.y; az += v.z; aw += v.w;
            }
        }
        p += cnt;
    }
    ax += __shfl_xor_sync(0xffffffffu, ax, 16);
    ay += __shfl_xor_sync(0xffffffffu, ay, 16);
    az += __shfl_xor_sync(0xffffffffu, az, 16);
    aw += __shfl_xor_sync(0xffffffffu, aw, 16);
    if (half == 0)
        ((float4*)(g_agg + (size_t)w * F))[q] = make_float4(ax, ay, az, aw);

    // ---- pre[w,f] = sum_k h[w,k] * Wr[f,k]; lane covers f = 2*lane, 2*lane+1
    const float2* h2p = (const float2*)(h + (size_t)w * 64);
    unsigned long long acc = 0ull;
    #pragma unroll 8
    for (int k2 = 0; k2 < 32; k2++) {
        float2 hv = h2p[k2];                          // uniform (broadcast) load
        const float* wb = wrs + (2 * k2) * WSTRIDE + 2 * lane;
        ffma2(acc, pack2(hv.x), *(const unsigned long long*)wb);
        ffma2(acc, pack2(hv.y), *(const unsigned long long*)(wb + WSTRIDE));
    }
    float2 pr = unpack2(acc);
    ((float2*)(g_pre + (size_t)w * 64))[lane] = pr;
}

// ---------------- lin: single GEMM agg@Wl^T + pre + bias (+tanh) ------------
__device__ __forceinline__ float fast_tanh(float x) {
    float e = __expf(2.f * x);
    return 1.f - 2.f / (e + 1.f);
}

#define LIN_THREADS 128
#define TILE_NODES  128
#define LIN_SMEM_FLOATS (64 * WSTRIDE + TILE_NODES * ASTRIDE)

__global__ void __launch_bounds__(LIN_THREADS)
lin_kernel(int hout_sel, float* __restrict__ dout,
           const float* __restrict__ Wl, const float* __restrict__ bl,
           int do_tanh) {
    extern __shared__ float sm[];
    float* wls = sm;                          // [64][WSTRIDE] k-major
    float* as_ = wls + 64 * WSTRIDE;          // [TILE_NODES][ASTRIDE]

    float* __restrict__ hout = (hout_sel < 0) ? dout : g_hbuf[hout_sel];

    for (int idx = threadIdx.x; idx < 64 * 64; idx += LIN_THREADS) {
        int f = idx >> 6, k = idx & 63;
        wls[k * WSTRIDE + f] = Wl[idx];
    }

    const int base = blockIdx.x * TILE_NODES;
    for (int v = threadIdx.x; v < TILE_NODES * 16; v += LIN_THREADS) {
        int node = v >> 4, kq = (v & 15) * 4;
        int gn = base + node;
        float4 va = make_float4(0.f, 0.f, 0.f, 0.f);
        if (gn < N_NODES)
            va = *(const float4*)(g_agg + (size_t)gn * 64 + kq);
        float* ap = as_ + node * ASTRIDE + kq;
        ap[0] = va.x; ap[1] = va.y; ap[2] = va.z; ap[3] = va.w;
    }
    __syncthreads();

    const int fx = threadIdx.x & 7;
    const int ny = threadIdx.x >> 3;
    const int f0 = fx * 8;
    const int n0 = ny * 8;

    unsigned long long acc[8][4];
    #pragma unroll
    for (int n = 0; n < 8; n++)
        #pragma unroll
        for (int jp = 0; jp < 4; jp++) acc[n][jp] = 0ull;

    #pragma unroll 8
    for (int k = 0; k < 64; k++) {
        const unsigned long long* wl64 =
            (const unsigned long long*)(wls + k * WSTRIDE + f0);
        unsigned long long wl[4];
        #pragma unroll
        for (int jp = 0; jp < 4; jp++) wl[jp] = wl64[jp];

        const float* ab = as_ + n0 * ASTRIDE + k;
        #pragma unroll
        for (int n = 0; n < 8; n++) {
            unsigned long long a2 = pack2(ab[n * ASTRIDE]);
            #pragma unroll
            for (int jp = 0; jp < 4; jp++)
                ffma2(acc[n][jp], a2, wl[jp]);
        }
    }

    float bias[8];
    #pragma unroll
    for (int j = 0; j < 8; j++) bias[j] = bl[f0 + j];

    #pragma unroll
    for (int n = 0; n < 8; n++) {
        int gn = base + n0 + n;
        if (gn >= N_NODES) continue;
        const float4* pp = (const float4*)(g_pre + (size_t)gn * 64 + f0);
        float4 pa = pp[0], pb = pp[1];
        float v[8];
        #pragma unroll
        for (int jp = 0; jp < 4; jp++) {
            float2 p = unpack2(acc[n][jp]);
            v[2 * jp]     = p.x + bias[2 * jp];
            v[2 * jp + 1] = p.y + bias[2 * jp + 1];
        }
        v[0] += pa.x; v[1] += pa.y; v[2] += pa.z; v[3] += pa.w;
        v[4] += pb.x; v[5] += pb.y; v[6] += pb.z; v[7] += pb.w;
        if (do_tanh) {
            #pragma unroll
            for (int j = 0; j < 8; j++) v[j] = fast_tanh(v[j]);
        }
        float* op = hout + (size_t)gn * 64 + f0;
        *(float4*)(op)     = make_float4(v[0], v[1], v[2], v[3]);
        *(float4*)(op + 4) = make_float4(v[4], v[5], v[6], v[7]);
    }
}

// ---------------- launch -----------------------------------------------------
extern "C" void kernel_launch(void* const* d_in, const int* in_sizes, int n_in,
                              void* d_out, int out_size) {
    const float* x      = (const float*)d_in[0];
    const void*  ei     = d_in[1];
    const float* Wl_in  = (const float*)d_in[2];
    const float* bl_in  = (const float*)d_in[3];
    const float* Wr_in  = (const float*)d_in[4];
    const float* Wl_med = (const float*)d_in[5];
    const float* bl_med = (const float*)d_in[6];
    const float* Wr_med = (const float*)d_in[7];
    const float* Wl_out = (const float*)d_in[8];
    const float* bl_out = (const float*)d_in[9];
    const float* Wr_out = (const float*)d_in[10];
    float*       out    = (float*)d_out;

    static int smem_set = 0;
    const int LIN_SMEM = LIN_SMEM_FLOATS * 4;   // 50,176 bytes
    if (!smem_set) {
        cudaFuncSetAttribute(lin_kernel,
                             cudaFuncAttributeMaxDynamicSharedMemorySize, LIN_SMEM);
        smem_set = 1;
    }

    // CSR build
    zerodetect_kernel<<<(N_NODES + 255) / 256, 256>>>((const int*)ei);
    count_kernel<<<1024, 256>>>(ei);
    part_sum_kernel<<<NPART, SCAN_BLK>>>();
    part_scan_kernel<<<1, 512>>>();
    offsets_kernel<<<NPART, SCAN_BLK>>>();
    fill_kernel<<<1024, 256>>>(ei);

    const int AGG_BLOCKS = (N_NODES * 32 + 255) / 256;      // 1 warp / node
    const int LIN_BLOCKS = (N_NODES + TILE_NODES - 1) / TILE_NODES;  // 782

    agg_kernel<<<AGG_BLOCKS, 256>>>(x, -1, Wr_in);
    lin_kernel<<<LIN_BLOCKS, LIN_THREADS, LIN_SMEM>>>(0, nullptr, Wl_in, bl_in, 1);
    agg_kernel<<<AGG_BLOCKS, 256>>>(nullptr, 0, Wr_med);
    lin_kernel<<<LIN_BLOCKS, LIN_THREADS, LIN_SMEM>>>(1, nullptr, Wl_med, bl_med, 1);
    agg_kernel<<<AGG_BLOCKS, 256>>>(nullptr, 1, Wr_med);
    lin_kernel<<<LIN_BLOCKS, LIN_THREADS, LIN_SMEM>>>(0, nullptr, Wl_med, bl_med, 1);
    agg_kernel<<<AGG_BLOCKS, 256>>>(nullptr, 0, Wr_out);
    lin_kernel<<<LIN_BLOCKS, LIN_THREADS, LIN_SMEM>>>(-1, out, Wl_out, bl_out, 0);
}

// round 11
// speedup vs baseline: 1.5726x; 1.5726x over previous
#include <cuda_runtime.h>

#define N_NODES 100000
#define E_EDGES 1200000
#define F 64

#define SCAN_BLK 256
#define NPART ((N_NODES + SCAN_BLK - 1) / SCAN_BLK)   // 391

typedef unsigned long long u64;

// ---------------- scratch (device globals; no allocation allowed) ----------
__device__ int   g_is64;
__device__ int   g_cnt[N_NODES];
__device__ int   g_cur[N_NODES];
__device__ int   g_off[N_NODES + 1];
__device__ int   g_part[NPART];
__device__ int   g_pscan[NPART];
__device__ int   g_srcs[E_EDGES];
__device__ __align__(16) float g_agg[N_NODES * F];
__device__ __align__(16) float g_hbuf[2][N_NODES * F];

// ---------------- FFMA2 helpers ----------------------------------------------
__device__ __forceinline__ u64 pack_ab(float a, float b) {
    u64 r;
    asm("mov.b64 %0, {%1, %2};" : "=l"(r) : "f"(a), "f"(b));
    return r;
}
__device__ __forceinline__ void ffma2(u64& acc, u64 a, u64 b) {
    asm("fma.rn.f32x2 %0, %1, %2, %0;" : "+l"(acc) : "l"(a), "l"(b));
}
__device__ __forceinline__ float2 unpack2(u64 v) {
    float lo, hi;
    asm("mov.b64 {%0, %1}, %2;" : "=f"(lo), "=f"(hi) : "l"(v));
    return make_float2(lo, hi);
}

// ---------------- zero + dtype detection (merged) ---------------------------
// int64 indices (< 2^31, little-endian): all odd int32 words of src are zero.
__global__ void zerodetect_kernel(const int* __restrict__ ei32) {
    int i = blockIdx.x * blockDim.x + threadIdx.x;
    if (i < N_NODES) { g_cnt[i] = 0; g_cur[i] = 0; }
    if (blockIdx.x == 0) {
        __shared__ int any;
        if (threadIdx.x == 0) any = 0;
        __syncthreads();
        int acc = 0;
        for (int j = threadIdx.x * 2 + 1; j < 4096; j += 2 * blockDim.x)
            acc |= ei32[j];
        if (acc) atomicOr(&any, 1);
        __syncthreads();
        if (threadIdx.x == 0) g_is64 = (any == 0) ? 1 : 0;
    }
}

__device__ __forceinline__ int load_idx(const void* ei, long long pos, bool is64) {
    if (is64) return (int)((const long long*)ei)[pos];
    return ((const int*)ei)[pos];
}

// ---------------- CSR build -------------------------------------------------
__global__ void count_kernel(const void* __restrict__ ei) {
    const bool is64 = (g_is64 != 0);
    int stride = gridDim.x * blockDim.x;
    for (int e = blockIdx.x * blockDim.x + threadIdx.x; e < E_EDGES; e += stride) {
        int d = load_idx(ei, (long long)E_EDGES + e, is64);
        if ((unsigned)d < (unsigned)N_NODES)
            atomicAdd(&g_cnt[d], 1);
    }
}

__global__ void part_sum_kernel() {
    __shared__ int red[SCAN_BLK];
    int i = blockIdx.x * SCAN_BLK + threadIdx.x;
    red[threadIdx.x] = (i < N_NODES) ? g_cnt[i] : 0;
    __syncthreads();
    for (int s = SCAN_BLK / 2; s > 0; s >>= 1) {
        if (threadIdx.x < s) red[threadIdx.x] += red[threadIdx.x + s];
        __syncthreads();
    }
    if (threadIdx.x == 0) g_part[blockIdx.x] = red[0];
}

__global__ void part_scan_kernel() {
    __shared__ int s[512];
    int t = threadIdx.x;
    int v = (t < NPART) ? g_part[t] : 0;
    s[t] = v;
    __syncthreads();
    for (int off = 1; off < 512; off <<= 1) {
        int u = (t >= off) ? s[t - off] : 0;
        __syncthreads();
        s[t] += u;
        __syncthreads();
    }
    if (t < NPART) g_pscan[t] = s[t] - v;
    if (t == 511) g_off[N_NODES] = s[511];
}

__global__ void offsets_kernel() {
    __shared__ int s[SCAN_BLK];
    int t = threadIdx.x;
    int i = blockIdx.x * SCAN_BLK + t;
    int v = (i < N_NODES) ? g_cnt[i] : 0;
    s[t] = v;
    __syncthreads();
    for (int off = 1; off < SCAN_BLK; off <<= 1) {
        int u = (t >= off) ? s[t - off] : 0;
        __syncthreads();
        s[t] += u;
        __syncthreads();
    }
    if (i < N_NODES) g_off[i] = g_pscan[blockIdx.x] + s[t] - v;
}

__global__ void fill_kernel(const void* __restrict__ ei) {
    const bool is64 = (g_is64 != 0);
    int stride = gridDim.x * blockDim.x;
    for (int e = blockIdx.x * blockDim.x + threadIdx.x; e < E_EDGES; e += stride) {
        int d = load_idx(ei, (long long)E_EDGES + e, is64);
        int s = load_idx(ei, (long long)e, is64);
        if ((unsigned)d < (unsigned)N_NODES && (unsigned)s < (unsigned)N_NODES) {
            int p = g_off[d] + atomicAdd(&g_cur[d], 1);
            g_srcs[p] = s;
        }
    }
}

// ---------------- aggregation: one warp per node (R8 best shape) ------------
__global__ void __launch_bounds__(256)
agg_kernel(const float* __restrict__ x, int hin_sel) {
    const float* __restrict__ h = (hin_sel < 0) ? x : g_hbuf[hin_sel];
    int w = (blockIdx.x * blockDim.x + threadIdx.x) >> 5;
    int lane = threadIdx.x & 31;
    if (w >= N_NODES) return;

    const int q = lane & 15;        // float4 slot within row
    const int half = lane >> 4;     // 0: even edges, 1: odd edges

    float ax = 0.f, ay = 0.f, az = 0.f, aw = 0.f;
    int p = g_off[w], pe = g_off[w + 1];
    while (p < pe) {
        int cnt = pe - p; if (cnt > 32) cnt = 32;
        int idx = (lane < cnt) ? g_srcs[p + lane] : 0;
        int j = 0;
        for (; j + 4 <= cnt; j += 4) {
            int s0 = __shfl_sync(0xffffffffu, idx, j + half);
            int s1 = __shfl_sync(0xffffffffu, idx, j + 2 + half);
            float4 v0 = ((const float4*)(h + (size_t)s0 * 64))[q];
            float4 v1 = ((const float4*)(h + (size_t)s1 * 64))[q];
            ax += v0.x + v1.x; ay += v0.y + v1.y;
            az += v0.z + v1.z; aw += v0.w + v1.w;
        }
        for (; j < cnt; j += 2) {
            int e = j + half;
            int s0 = __shfl_sync(0xffffffffu, idx, e & 31);
            if (e < cnt) {
                float4 v = ((const float4*)(h + (size_t)s0 * 64))[q];
                ax += v.x; ay += v.y; az += v.z; aw += v.w;
            }
        }
        p += cnt;
    }
    ax += __shfl_xor_sync(0xffffffffu, ax, 16);
    ay += __shfl_xor_sync(0xffffffffu, ay, 16);
    az += __shfl_xor_sync(0xffffffffu, az, 16);
    aw += __shfl_xor_sync(0xffffffffu, aw, 16);
    if (half == 0)
        ((float4*)(g_agg + (size_t)w * F))[q] = make_float4(ax, ay, az, aw);
}

// ---------------- lin: PACKED dual GEMM -------------------------------------
// smem act word  = (agg[n,k], h[n,k]); smem weight word = (Wl[f,k], Wr[f,k]).
// One FFMA2 advances both GEMMs; epilogue sums the two halves.
__device__ __forceinline__ float fast_tanh(float x) {
    float e = __expf(2.f * x);
    return 1.f - 2.f / (e + 1.f);
}

#define LIN_THREADS 256
#define TILE_NODES  128
#define WST2 65                     // u64 stride for weights
#define AST2 65                     // u64 stride for acts
#define LIN_SMEM_BYTES ((64 * WST2 + TILE_NODES * AST2) * 8)   // 99,840

__global__ void __launch_bounds__(LIN_THREADS)
lin_kernel(const float* __restrict__ x, int hin_sel, int hout_sel,
           float* __restrict__ dout,
           const float* __restrict__ Wl, const float* __restrict__ bl,
           const float* __restrict__ Wr, int do_tanh) {
    extern __shared__ u64 smu[];
    u64* wpk = smu;                 // [64][WST2]  (wl,wr) k-major
    u64* apk = smu + 64 * WST2;     // [TILE_NODES][AST2]  (agg,h)

    const float* __restrict__ hin = (hin_sel < 0) ? x : g_hbuf[hin_sel];
    float* __restrict__ hout = (hout_sel < 0) ? dout : g_hbuf[hout_sel];

    const int tid = threadIdx.x;
    // weights: coalesced LDG of Wl/Wr, interleaved STS.64
    for (int idx = tid; idx < 64 * 64; idx += LIN_THREADS) {
        int f = idx >> 6, k = idx & 63;
        wpk[k * WST2 + f] = pack_ab(Wl[idx], Wr[idx]);
    }

    const int base = blockIdx.x * TILE_NODES;
    // acts: float4 LDG of agg + h, interleaved STS.64
    for (int v = tid; v < TILE_NODES * 16; v += LIN_THREADS) {
        int node = v >> 4, kq = (v & 15) * 4;
        int gn = base + node;
        float4 va = make_float4(0.f, 0.f, 0.f, 0.f);
        float4 vh = va;
        if (gn < N_NODES) {
            va = *(const float4*)(g_agg + (size_t)gn * 64 + kq);
            vh = *(const float4*)(hin   + (size_t)gn * 64 + kq);
        }
        u64* ap = apk + node * AST2 + kq;
        ap[0] = pack_ab(va.x, vh.x);
        ap[1] = pack_ab(va.y, vh.y);
        ap[2] = pack_ab(va.z, vh.z);
        ap[3] = pack_ab(va.w, vh.w);
    }
    __syncthreads();

    const int fx = tid & 15;        // 16 output groups of 4
    const int ny = tid >> 4;        // 16 node groups of 8
    const int f0 = fx * 4;
    const int n0 = ny * 8;

    u64 acc[8][4];
    #pragma unroll
    for (int n = 0; n < 8; n++)
        #pragma unroll
        for (int j = 0; j < 4; j++) acc[n][j] = 0ull;

    #pragma unroll 8
    for (int k = 0; k < 64; k++) {
        u64 w2[4];
        const u64* wb = wpk + k * WST2 + f0;
        #pragma unroll
        for (int j = 0; j < 4; j++) w2[j] = wb[j];

        const u64* ap = apk + n0 * AST2 + k;
        #pragma unroll
        for (int n = 0; n < 8; n++) {
            u64 a2 = ap[n * AST2];
            #pragma unroll
            for (int j = 0; j < 4; j++)
                ffma2(acc[n][j], a2, w2[j]);
        }
    }

    float bias[4];
    #pragma unroll
    for (int j = 0; j < 4; j++) bias[j] = bl[f0 + j];

    #pragma unroll
    for (int n = 0; n < 8; n++) {
        int gn = base + n0 + n;
        if (gn >= N_NODES) continue;
        float v[4];
        #pragma unroll
        for (int j = 0; j < 4; j++) {
            float2 p = unpack2(acc[n][j]);
            v[j] = p.x + p.y + bias[j];          // agg@Wl + h@Wr + b
        }
        if (do_tanh) {
            #pragma unroll
            for (int j = 0; j < 4; j++) v[j] = fast_tanh(v[j]);
        }
        *(float4*)(hout + (size_t)gn * 64 + f0) =
            make_float4(v[0], v[1], v[2], v[3]);
    }
}

// ---------------- launch -----------------------------------------------------
extern "C" void kernel_launch(void* const* d_in, const int* in_sizes, int n_in,
                              void* d_out, int out_size) {
    const float* x      = (const float*)d_in[0];
    const void*  ei     = d_in[1];
    const float* Wl_in  = (const float*)d_in[2];
    const float* bl_in  = (const float*)d_in[3];
    const float* Wr_in  = (const float*)d_in[4];
    const float* Wl_med = (const float*)d_in[5];
    const float* bl_med = (const float*)d_in[6];
    const float* Wr_med = (const float*)d_in[7];
    const float* Wl_out = (const float*)d_in[8];
    const float* bl_out = (const float*)d_in[9];
    const float* Wr_out = (const float*)d_in[10];
    float*       out    = (float*)d_out;

    static int smem_set = 0;
    if (!smem_set) {
        cudaFuncSetAttribute(lin_kernel,
                             cudaFuncAttributeMaxDynamicSharedMemorySize,
                             LIN_SMEM_BYTES);
        smem_set = 1;
    }

    // CSR build
    zerodetect_kernel<<<(N_NODES + 255) / 256, 256>>>((const int*)ei);
    count_kernel<<<1024, 256>>>(ei);
    part_sum_kernel<<<NPART, SCAN_BLK>>>();
    part_scan_kernel<<<1, 512>>>();
    offsets_kernel<<<NPART, SCAN_BLK>>>();
    fill_kernel<<<1024, 256>>>(ei);

    const int AGG_BLOCKS = (N_NODES * 32 + 255) / 256;      // 1 warp / node
    const int LIN_BLOCKS = (N_NODES + TILE_NODES - 1) / TILE_NODES;  // 782

    agg_kernel<<<AGG_BLOCKS, 256>>>(x, -1);
    lin_kernel<<<LIN_BLOCKS, LIN_THREADS, LIN_SMEM_BYTES>>>(
        x, -1, 0, nullptr, Wl_in, bl_in, Wr_in, 1);
    agg_kernel<<<AGG_BLOCKS, 256>>>(nullptr, 0);
    lin_kernel<<<LIN_BLOCKS, LIN_THREADS, LIN_SMEM_BYTES>>>(
        nullptr, 0, 1, nullptr, Wl_med, bl_med, Wr_med, 1);
    agg_kernel<<<AGG_BLOCKS, 256>>>(nullptr, 1);
    lin_kernel<<<LIN_BLOCKS, LIN_THREADS, LIN_SMEM_BYTES>>>(
        nullptr, 1, 0, nullptr, Wl_med, bl_med, Wr_med, 1);
    agg_kernel<<<AGG_BLOCKS, 256>>>(nullptr, 0);
    lin_kernel<<<LIN_BLOCKS, LIN_THREADS, LIN_SMEM_BYTES>>>(
        nullptr, 0, -1, out, Wl_out, bl_out, Wr_out, 0);
}

// round 12
// speedup vs baseline: 1.6625x; 1.0572x over previous
#include <cuda_runtime.h>

#define N_NODES 100000
#define E_EDGES 1200000
#define F 64

#define SCAN_BLK 256
#define NPART ((N_NODES + SCAN_BLK - 1) / SCAN_BLK)   // 391

// ---------------- scratch (device globals; no allocation allowed) ----------
__device__ int   g_is64;
__device__ int   g_cnt[N_NODES];
__device__ int   g_cur[N_NODES];
__device__ int   g_off[N_NODES + 1];
__device__ int   g_part[NPART];
__device__ int   g_flag[NPART];
__device__ int   g_srcs[E_EDGES];
__device__ __align__(16) float g_agg[N_NODES * F];
__device__ __align__(16) float g_hbuf[2][N_NODES * F];

// ---------------- zero + dtype detection (merged) ---------------------------
// int64 indices (< 2^31, little-endian): all odd int32 words of src are zero.
__global__ void zerodetect_kernel(const int* __restrict__ ei32) {
    int i = blockIdx.x * blockDim.x + threadIdx.x;
    if (i < N_NODES) { g_cnt[i] = 0; g_cur[i] = 0; }
    if (i < NPART)   g_flag[i] = 0;
    if (blockIdx.x == 0) {
        __shared__ int any;
        if (threadIdx.x == 0) any = 0;
        __syncthreads();
        int acc = 0;
        for (int j = threadIdx.x * 2 + 1; j < 4096; j += 2 * blockDim.x)
            acc |= ei32[j];
        if (acc) atomicOr(&any, 1);
        __syncthreads();
        if (threadIdx.x == 0) g_is64 = (any == 0) ? 1 : 0;
    }
}

__device__ __forceinline__ int load_idx(const void* ei, long long pos, bool is64) {
    if (is64) return (int)((const long long*)ei)[pos];
    return ((const int*)ei)[pos];
}

// ---------------- CSR build -------------------------------------------------
__global__ void count_kernel(const void* __restrict__ ei) {
    const bool is64 = (g_is64 != 0);
    int stride = gridDim.x * blockDim.x;
    for (int e = blockIdx.x * blockDim.x + threadIdx.x; e < E_EDGES; e += stride) {
        int d = load_idx(ei, (long long)E_EDGES + e, is64);
        if ((unsigned)d < (unsigned)N_NODES)
            atomicAdd(&g_cnt[d], 1);
    }
}

// single-kernel scan: per-block inclusive scan + decoupled aggregate lookback
__global__ void scan_offsets_kernel() {
    __shared__ int s[SCAN_BLK];
    __shared__ int sbase;
    const int t = threadIdx.x, b = blockIdx.x;
    const int i = b * SCAN_BLK + t;
    const int v = (i < N_NODES) ? g_cnt[i] : 0;
    s[t] = v;
    __syncthreads();
    for (int off = 1; off < SCAN_BLK; off <<= 1) {
        int u = (t >= off) ? s[t - off] : 0;
        __syncthreads();
        s[t] += u;
        __syncthreads();
    }
    // post this block's aggregate (release)
    if (t == SCAN_BLK - 1) {
        atomicExch(&g_part[b], s[t]);
        __threadfence();
        atomicExch(&g_flag[b], 1);
    }
    // warp 0: sum aggregates of predecessor blocks (warp-parallel spin)
    if (t < 32) {
        int sum = 0;
        for (int j0 = 0; j0 < b; j0 += 32) {
            int j = j0 + t;
            int a = 0;
            if (j < b) {
                while (atomicAdd(&g_flag[j], 0) == 0) {}
                a = atomicAdd(&g_part[j], 0);
            }
            #pragma unroll
            for (int o = 16; o; o >>= 1)
                a += __shfl_down_sync(0xffffffffu, a, o);
            if (t == 0) sum += a;
        }
        if (t == 0) sbase = sum;
    }
    __syncthreads();
    const int base = sbase;
    if (i < N_NODES) g_off[i] = base + s[t] - v;           // exclusive
    if (b == (int)gridDim.x - 1 && t == SCAN_BLK - 1)
        g_off[N_NODES] = base + s[t];                      // total valid edges
}

__global__ void fill_kernel(const void* __restrict__ ei) {
    const bool is64 = (g_is64 != 0);
    int stride = gridDim.x * blockDim.x;
    for (int e = blockIdx.x * blockDim.x + threadIdx.x; e < E_EDGES; e += stride) {
        int d = load_idx(ei, (long long)E_EDGES + e, is64);
        int s = load_idx(ei, (long long)e, is64);
        if ((unsigned)d < (unsigned)N_NODES && (unsigned)s < (unsigned)N_NODES) {
            int p = g_off[d] + atomicAdd(&g_cur[d], 1);
            g_srcs[p] = s;
        }
    }
}

// ---------------- aggregation: one warp per node (R8 best shape) ------------
__global__ void __launch_bounds__(256)
agg_kernel(const float* __restrict__ x, int hin_sel) {
    const float* __restrict__ h = (hin_sel < 0) ? x : g_hbuf[hin_sel];
    int w = (blockIdx.x * blockDim.x + threadIdx.x) >> 5;
    int lane = threadIdx.x & 31;
    if (w >= N_NODES) return;

    const int q = lane & 15;        // float4 slot within row
    const int half = lane >> 4;     // 0: even edges, 1: odd edges

    float ax = 0.f, ay = 0.f, az = 0.f, aw = 0.f;
    int p = g_off[w], pe = g_off[w + 1];
    while (p < pe) {
        int cnt = pe - p; if (cnt > 32) cnt = 32;
        int idx = (lane < cnt) ? g_srcs[p + lane] : 0;
        int j = 0;
        for (; j + 4 <= cnt; j += 4) {
            int s0 = __shfl_sync(0xffffffffu, idx, j + half);
            int s1 = __shfl_sync(0xffffffffu, idx, j + 2 + half);
            float4 v0 = ((const float4*)(h + (size_t)s0 * 64))[q];
            float4 v1 = ((const float4*)(h + (size_t)s1 * 64))[q];
            ax += v0.x + v1.x; ay += v0.y + v1.y;
            az += v0.z + v1.z; aw += v0.w + v1.w;
        }
        for (; j < cnt; j += 2) {
            int e = j + half;
            int s0 = __shfl_sync(0xffffffffu, idx, e & 31);
            if (e < cnt) {
                float4 v = ((const float4*)(h + (size_t)s0 * 64))[q];
                ax += v.x; ay += v.y; az += v.z; aw += v.w;
            }
        }
        p += cnt;
    }
    ax += __shfl_xor_sync(0xffffffffu, ax, 16);
    ay += __shfl_xor_sync(0xffffffffu, ay, 16);
    az += __shfl_xor_sync(0xffffffffu, az, 16);
    aw += __shfl_xor_sync(0xffffffffu, aw, 16);
    if (half == 0)
        ((float4*)(g_agg + (size_t)w * F))[q] = make_float4(ax, ay, az, aw);
}

// ---------------- fused dual-GEMM + bias (+tanh), FFMA2 path (R3 shape) -----
__device__ __forceinline__ float fast_tanh(float x) {
    float e = __expf(2.f * x);
    return 1.f - 2.f / (e + 1.f);
}

#define LIN_THREADS 128
#define TILE_NODES  128
#define ASTRIDE     65
#define WSTRIDE     66
#define LIN_SMEM_FLOATS (2 * 64 * WSTRIDE + 2 * TILE_NODES * ASTRIDE)

__device__ __forceinline__ unsigned long long pack2(float v) {
    unsigned long long r;
    asm("mov.b64 %0, {%1, %1};" : "=l"(r) : "f"(v));
    return r;
}
__device__ __forceinline__ void ffma2(unsigned long long& acc, unsigned long long a,
                                      unsigned long long b) {
    asm("fma.rn.f32x2 %0, %1, %2, %0;" : "+l"(acc) : "l"(a), "l"(b));
}
__device__ __forceinline__ float2 unpack2(unsigned long long v) {
    float lo, hi;
    asm("mov.b64 {%0, %1}, %2;" : "=f"(lo), "=f"(hi) : "l"(v));
    return make_float2(lo, hi);
}

__global__ void __launch_bounds__(LIN_THREADS)
lin_kernel(const float* __restrict__ x, int hin_sel, int hout_sel,
           float* __restrict__ dout,
           const float* __restrict__ Wl, const float* __restrict__ bl,
           const float* __restrict__ Wr, int do_tanh) {
    extern __shared__ float sm[];
    float* wls = sm;                          // [64][WSTRIDE] k-major
    float* wrs = wls + 64 * WSTRIDE;
    float* as_ = wrs + 64 * WSTRIDE;          // [TILE_NODES][ASTRIDE]
    float* hs_ = as_ + TILE_NODES * ASTRIDE;

    const float* __restrict__ hin = (hin_sel < 0) ? x : g_hbuf[hin_sel];
    float* __restrict__ hout = (hout_sel < 0) ? dout : g_hbuf[hout_sel];

    for (int idx = threadIdx.x; idx < 64 * 64; idx += LIN_THREADS) {
        int f = idx >> 6, k = idx & 63;
        wls[k * WSTRIDE + f] = Wl[idx];
        wrs[k * WSTRIDE + f] = Wr[idx];
    }

    const int base = blockIdx.x * TILE_NODES;
    for (int v = threadIdx.x; v < TILE_NODES * 16; v += LIN_THREADS) {
        int node = v >> 4, kq = (v & 15) * 4;
        int gn = base + node;
        float4 va = make_float4(0.f, 0.f, 0.f, 0.f);
        float4 vh = va;
        if (gn < N_NODES) {
            va = *(const float4*)(g_agg + (size_t)gn * 64 + kq);
            vh = *(const float4*)(hin   + (size_t)gn * 64 + kq);
        }
        float* ap = as_ + node * ASTRIDE + kq;
        ap[0] = va.x; ap[1] = va.y; ap[2] = va.z; ap[3] = va.w;
        float* hp = hs_ + node * ASTRIDE + kq;
        hp[0] = vh.x; hp[1] = vh.y; hp[2] = vh.z; hp[3] = vh.w;
    }
    __syncthreads();

    const int fx = threadIdx.x & 7;
    const int ny = threadIdx.x >> 3;
    const int f0 = fx * 8;
    const int n0 = ny * 8;

    unsigned long long acc[8][4];
    #pragma unroll
    for (int n = 0; n < 8; n++)
        #pragma unroll
        for (int jp = 0; jp < 4; jp++) acc[n][jp] = 0ull;

    #pragma unroll 8
    for (int k = 0; k < 64; k++) {
        const unsigned long long* wl64 =
            (const unsigned long long*)(wls + k * WSTRIDE + f0);
        const unsigned long long* wr64 =
            (const unsigned long long*)(wrs + k * WSTRIDE + f0);
        unsigned long long wl[4], wr[4];
        #pragma unroll
        for (int jp = 0; jp < 4; jp++) { wl[jp] = wl64[jp]; wr[jp] = wr64[jp]; }

        const float* ab = as_ + n0 * ASTRIDE + k;
        const float* hb = hs_ + n0 * ASTRIDE + k;
        #pragma unroll
        for (int n = 0; n < 8; n++) {
            unsigned long long a2 = pack2(ab[n * ASTRIDE]);
            unsigned long long h2 = pack2(hb[n * ASTRIDE]);
            #pragma unroll
            for (int jp = 0; jp < 4; jp++) {
                ffma2(acc[n][jp], a2, wl[jp]);
                ffma2(acc[n][jp], h2, wr[jp]);
            }
        }
    }

    float bias[8];
    #pragma unroll
    for (int j = 0; j < 8; j++) bias[j] = bl[f0 + j];

    #pragma unroll
    for (int n = 0; n < 8; n++) {
        int gn = base + n0 + n;
        if (gn >= N_NODES) continue;
        float v[8];
        #pragma unroll
        for (int jp = 0; jp < 4; jp++) {
            float2 p = unpack2(acc[n][jp]);
            v[2 * jp]     = p.x + bias[2 * jp];
            v[2 * jp + 1] = p.y + bias[2 * jp + 1];
        }
        if (do_tanh) {
            #pragma unroll
            for (int j = 0; j < 8; j++) v[j] = fast_tanh(v[j]);
        }
        float* op = hout + (size_t)gn * 64 + f0;
        *(float4*)(op)     = make_float4(v[0], v[1], v[2], v[3]);
        *(float4*)(op + 4) = make_float4(v[4], v[5], v[6], v[7]);
    }
}

// ---------------- launch -----------------------------------------------------
extern "C" void kernel_launch(void* const* d_in, const int* in_sizes, int n_in,
                              void* d_out, int out_size) {
    const float* x      = (const float*)d_in[0];
    const void*  ei     = d_in[1];
    const float* Wl_in  = (const float*)d_in[2];
    const float* bl_in  = (const float*)d_in[3];
    const float* Wr_in  = (const float*)d_in[4];
    const float* Wl_med = (const float*)d_in[5];
    const float* bl_med = (const float*)d_in[6];
    const float* Wr_med = (const float*)d_in[7];
    const float* Wl_out = (const float*)d_in[8];
    const float* bl_out = (const float*)d_in[9];
    const float* Wr_out = (const float*)d_in[10];
    float*       out    = (float*)d_out;

    static int smem_set = 0;
    const int LIN_SMEM = LIN_SMEM_FLOATS * 4;   // 100,352 bytes
    if (!smem_set) {
        cudaFuncSetAttribute(lin_kernel,
                             cudaFuncAttributeMaxDynamicSharedMemorySize, LIN_SMEM);
        smem_set = 1;
    }

    // CSR build: 4 kernels (zero+detect, count, lookback scan, fill)
    zerodetect_kernel<<<(N_NODES + 255) / 256, 256>>>((const int*)ei);
    count_kernel<<<1024, 256>>>(ei);
    scan_offsets_kernel<<<NPART, SCAN_BLK>>>();
    fill_kernel<<<1024, 256>>>(ei);

    const int AGG_BLOCKS = (N_NODES * 32 + 255) / 256;      // 1 warp / node
    const int LIN_BLOCKS = (N_NODES + TILE_NODES - 1) / TILE_NODES;  // 782

    agg_kernel<<<AGG_BLOCKS, 256>>>(x, -1);
    lin_kernel<<<LIN_BLOCKS, LIN_THREADS, LIN_SMEM>>>(x, -1, 0, nullptr,
                                                      Wl_in, bl_in, Wr_in, 1);
    agg_kernel<<<AGG_BLOCKS, 256>>>(nullptr, 0);
    lin_kernel<<<LIN_BLOCKS, LIN_THREADS, LIN_SMEM>>>(nullptr, 0, 1, nullptr,
                                                      Wl_med, bl_med, Wr_med, 1);
    agg_kernel<<<AGG_BLOCKS, 256>>>(nullptr, 1);
    lin_kernel<<<LIN_BLOCKS, LIN_THREADS, LIN_SMEM>>>(nullptr, 1, 0, nullptr,
                                                      Wl_med, bl_med, Wr_med, 1);
    agg_kernel<<<AGG_BLOCKS, 256>>>(nullptr, 0);
    lin_kernel<<<LIN_BLOCKS, LIN_THREADS, LIN_SMEM>>>(nullptr, 0, -1, out,
                                                      Wl_out, bl_out, Wr_out, 0);
}

// round 13
// speedup vs baseline: 1.7195x; 1.0342x over previous
#include <cuda_runtime.h>

#define N_NODES 100000
#define E_EDGES 1200000
#define F 64

#define SCAN_BLK 256
#define NPART ((N_NODES + SCAN_BLK - 1) / SCAN_BLK)   // 391

// ---------------- scratch (device globals; no allocation allowed) ----------
__device__ int   g_is64;
__device__ int   g_cnt[N_NODES];
__device__ int   g_cur[N_NODES];      // starts as copy of offsets; fill bumps it
__device__ int   g_off[N_NODES + 1];
__device__ int   g_part[NPART];
__device__ int   g_pscan[NPART];
__device__ int   g_srcs[E_EDGES];
__device__ __align__(16) float g_agg[N_NODES * F];
__device__ __align__(16) float g_hbuf[2][N_NODES * F];

// ---------------- zero + dtype detection (merged) ---------------------------
// int64 indices (< 2^31, little-endian): all odd int32 words of src are zero.
__global__ void zerodetect_kernel(const int* __restrict__ ei32) {
    int i = blockIdx.x * blockDim.x + threadIdx.x;
    if (i < N_NODES) g_cnt[i] = 0;
    if (blockIdx.x == 0) {
        __shared__ int any;
        if (threadIdx.x == 0) any = 0;
        __syncthreads();
        int acc = 0;
        for (int j = threadIdx.x * 2 + 1; j < 4096; j += 2 * blockDim.x)
            acc |= ei32[j];
        if (acc) atomicOr(&any, 1);
        __syncthreads();
        if (threadIdx.x == 0) g_is64 = (any == 0) ? 1 : 0;
    }
}

// ---------------- CSR build -------------------------------------------------
// 4-way unrolled, vectorized index loads (E_EDGES % 4 == 0).
__global__ void count_kernel(const void* __restrict__ ei) {
    const bool is64 = (g_is64 != 0);
    const int stride = gridDim.x * blockDim.x;
    const int NG = E_EDGES / 4;
    for (int g = blockIdx.x * blockDim.x + threadIdx.x; g < NG; g += stride) {
        int d0, d1, d2, d3;
        if (is64) {
            const long long* dst = (const long long*)ei + E_EDGES + (size_t)g * 4;
            longlong2 a = ((const longlong2*)dst)[0];
            longlong2 b = ((const longlong2*)dst)[1];
            d0 = (int)a.x; d1 = (int)a.y; d2 = (int)b.x; d3 = (int)b.y;
        } else {
            int4 v = ((const int4*)((const int*)ei + E_EDGES))[g];
            d0 = v.x; d1 = v.y; d2 = v.z; d3 = v.w;
        }
        if ((unsigned)d0 < (unsigned)N_NODES) atomicAdd(&g_cnt[d0], 1);
        if ((unsigned)d1 < (unsigned)N_NODES) atomicAdd(&g_cnt[d1], 1);
        if ((unsigned)d2 < (unsigned)N_NODES) atomicAdd(&g_cnt[d2], 1);
        if ((unsigned)d3 < (unsigned)N_NODES) atomicAdd(&g_cnt[d3], 1);
    }
}

__global__ void part_sum_kernel() {
    __shared__ int red[SCAN_BLK];
    int i = blockIdx.x * SCAN_BLK + threadIdx.x;
    red[threadIdx.x] = (i < N_NODES) ? g_cnt[i] : 0;
    __syncthreads();
    for (int s = SCAN_BLK / 2; s > 0; s >>= 1) {
        if (threadIdx.x < s) red[threadIdx.x] += red[threadIdx.x + s];
        __syncthreads();
    }
    if (threadIdx.x == 0) g_part[blockIdx.x] = red[0];
}

__global__ void part_scan_kernel() {
    __shared__ int s[512];
    int t = threadIdx.x;
    int v = (t < NPART) ? g_part[t] : 0;
    s[t] = v;
    __syncthreads();
    for (int off = 1; off < 512; off <<= 1) {
        int u = (t >= off) ? s[t - off] : 0;
        __syncthreads();
        s[t] += u;
        __syncthreads();
    }
    if (t < NPART) g_pscan[t] = s[t] - v;
    if (t == 511) g_off[N_NODES] = s[511];
}

// per-block exclusive scan + base; writes BOTH g_off and g_cur (= offset)
__global__ void offsets_kernel() {
    __shared__ int s[SCAN_BLK];
    int t = threadIdx.x;
    int i = blockIdx.x * SCAN_BLK + t;
    int v = (i < N_NODES) ? g_cnt[i] : 0;
    s[t] = v;
    __syncthreads();
    for (int off = 1; off < SCAN_BLK; off <<= 1) {
        int u = (t >= off) ? s[t - off] : 0;
        __syncthreads();
        s[t] += u;
        __syncthreads();
    }
    if (i < N_NODES) {
        int o = g_pscan[blockIdx.x] + s[t] - v;
        g_off[i] = o;
        g_cur[i] = o;
    }
}

__global__ void fill_kernel(const void* __restrict__ ei) {
    const bool is64 = (g_is64 != 0);
    const int stride = gridDim.x * blockDim.x;
    const int NG = E_EDGES / 4;
    for (int g = blockIdx.x * blockDim.x + threadIdx.x; g < NG; g += stride) {
        int d0, d1, d2, d3, s0, s1, s2, s3;
        if (is64) {
            const long long* dst = (const long long*)ei + E_EDGES + (size_t)g * 4;
            const long long* src = (const long long*)ei + (size_t)g * 4;
            longlong2 a = ((const longlong2*)dst)[0];
            longlong2 b = ((const longlong2*)dst)[1];
            longlong2 c = ((const longlong2*)src)[0];
            longlong2 e = ((const longlong2*)src)[1];
            d0 = (int)a.x; d1 = (int)a.y; d2 = (int)b.x; d3 = (int)b.y;
            s0 = (int)c.x; s1 = (int)c.y; s2 = (int)e.x; s3 = (int)e.y;
        } else {
            int4 vd = ((const int4*)((const int*)ei + E_EDGES))[g];
            int4 vs = ((const int4*)ei)[g];
            d0 = vd.x; d1 = vd.y; d2 = vd.z; d3 = vd.w;
            s0 = vs.x; s1 = vs.y; s2 = vs.z; s3 = vs.w;
        }
        // single fused atomic per edge (g_cur pre-seeded with offsets)
        if ((unsigned)d0 < (unsigned)N_NODES && (unsigned)s0 < (unsigned)N_NODES)
            g_srcs[atomicAdd(&g_cur[d0], 1)] = s0;
        if ((unsigned)d1 < (unsigned)N_NODES && (unsigned)s1 < (unsigned)N_NODES)
            g_srcs[atomicAdd(&g_cur[d1], 1)] = s1;
        if ((unsigned)d2 < (unsigned)N_NODES && (unsigned)s2 < (unsigned)N_NODES)
            g_srcs[atomicAdd(&g_cur[d2], 1)] = s2;
        if ((unsigned)d3 < (unsigned)N_NODES && (unsigned)s3 < (unsigned)N_NODES)
            g_srcs[atomicAdd(&g_cur[d3], 1)] = s3;
    }
}

// ---------------- aggregation: one warp per node (R8 best shape) ------------
__global__ void __launch_bounds__(256)
agg_kernel(const float* __restrict__ x, int hin_sel) {
    const float* __restrict__ h = (hin_sel < 0) ? x : g_hbuf[hin_sel];
    int w = (blockIdx.x * blockDim.x + threadIdx.x) >> 5;
    int lane = threadIdx.x & 31;
    if (w >= N_NODES) return;

    const int q = lane & 15;        // float4 slot within row
    const int half = lane >> 4;     // 0: even edges, 1: odd edges

    float ax = 0.f, ay = 0.f, az = 0.f, aw = 0.f;
    int p = g_off[w], pe = g_off[w + 1];
    while (p < pe) {
        int cnt = pe - p; if (cnt > 32) cnt = 32;
        int idx = (lane < cnt) ? g_srcs[p + lane] : 0;
        int j = 0;
        for (; j + 4 <= cnt; j += 4) {
            int s0 = __shfl_sync(0xffffffffu, idx, j + half);
            int s1 = __shfl_sync(0xffffffffu, idx, j + 2 + half);
            float4 v0 = ((const float4*)(h + (size_t)s0 * 64))[q];
            float4 v1 = ((const float4*)(h + (size_t)s1 * 64))[q];
            ax += v0.x + v1.x; ay += v0.y + v1.y;
            az += v0.z + v1.z; aw += v0.w + v1.w;
        }
        for (; j < cnt; j += 2) {
            int e = j + half;
            int s0 = __shfl_sync(0xffffffffu, idx, e & 31);
            if (e < cnt) {
                float4 v = ((const float4*)(h + (size_t)s0 * 64))[q];
                ax += v.x; ay += v.y; az += v.z; aw += v.w;
            }
        }
        p += cnt;
    }
    ax += __shfl_xor_sync(0xffffffffu, ax, 16);
    ay += __shfl_xor_sync(0xffffffffu, ay, 16);
    az += __shfl_xor_sync(0xffffffffu, az, 16);
    aw += __shfl_xor_sync(0xffffffffu, aw, 16);
    if (half == 0)
        ((float4*)(g_agg + (size_t)w * F))[q] = make_float4(ax, ay, az, aw);
}

// ---------------- fused dual-GEMM + bias (+tanh), FFMA2 path (R3 shape) -----
__device__ __forceinline__ float fast_tanh(float x) {
    float e = __expf(2.f * x);
    return 1.f - 2.f / (e + 1.f);
}

#define LIN_THREADS 128
#define TILE_NODES  128
#define ASTRIDE     65
#define WSTRIDE     66
#define LIN_SMEM_FLOATS (2 * 64 * WSTRIDE + 2 * TILE_NODES * ASTRIDE)

__device__ __forceinline__ unsigned long long pack2(float v) {
    unsigned long long r;
    asm("mov.b64 %0, {%1, %1};" : "=l"(r) : "f"(v));
    return r;
}
__device__ __forceinline__ void ffma2(unsigned long long& acc, unsigned long long a,
                                      unsigned long long b) {
    asm("fma.rn.f32x2 %0, %1, %2, %0;" : "+l"(acc) : "l"(a), "l"(b));
}
__device__ __forceinline__ float2 unpack2(unsigned long long v) {
    float lo, hi;
    asm("mov.b64 {%0, %1}, %2;" : "=f"(lo), "=f"(hi) : "l"(v));
    return make_float2(lo, hi);
}

__global__ void __launch_bounds__(LIN_THREADS)
lin_kernel(const float* __restrict__ x, int hin_sel, int hout_sel,
           float* __restrict__ dout,
           const float* __restrict__ Wl, const float* __restrict__ bl,
           const float* __restrict__ Wr, int do_tanh) {
    extern __shared__ float sm[];
    float* wls = sm;                          // [64][WSTRIDE] k-major
    float* wrs = wls + 64 * WSTRIDE;
    float* as_ = wrs + 64 * WSTRIDE;          // [TILE_NODES][ASTRIDE]
    float* hs_ = as_ + TILE_NODES * ASTRIDE;

    const float* __restrict__ hin = (hin_sel < 0) ? x : g_hbuf[hin_sel];
    float* __restrict__ hout = (hout_sel < 0) ? dout : g_hbuf[hout_sel];

    for (int idx = threadIdx.x; idx < 64 * 64; idx += LIN_THREADS) {
        int f = idx >> 6, k = idx & 63;
        wls[k * WSTRIDE + f] = Wl[idx];
        wrs[k * WSTRIDE + f] = Wr[idx];
    }

    const int base = blockIdx.x * TILE_NODES;
    for (int v = threadIdx.x; v < TILE_NODES * 16; v += LIN_THREADS) {
        int node = v >> 4, kq = (v & 15) * 4;
        int gn = base + node;
        float4 va = make_float4(0.f, 0.f, 0.f, 0.f);
        float4 vh = va;
        if (gn < N_NODES) {
            va = *(const float4*)(g_agg + (size_t)gn * 64 + kq);
            vh = *(const float4*)(hin   + (size_t)gn * 64 + kq);
        }
        float* ap = as_ + node * ASTRIDE + kq;
        ap[0] = va.x; ap[1] = va.y; ap[2] = va.z; ap[3] = va.w;
        float* hp = hs_ + node * ASTRIDE + kq;
        hp[0] = vh.x; hp[1] = vh.y; hp[2] = vh.z; hp[3] = vh.w;
    }
    __syncthreads();

    const int fx = threadIdx.x & 7;
    const int ny = threadIdx.x >> 3;
    const int f0 = fx * 8;
    const int n0 = ny * 8;

    unsigned long long acc[8][4];
    #pragma unroll
    for (int n = 0; n < 8; n++)
        #pragma unroll
        for (int jp = 0; jp < 4; jp++) acc[n][jp] = 0ull;

    #pragma unroll 8
    for (int k = 0; k < 64; k++) {
        const unsigned long long* wl64 =
            (const unsigned long long*)(wls + k * WSTRIDE + f0);
        const unsigned long long* wr64 =
            (const unsigned long long*)(wrs + k * WSTRIDE + f0);
        unsigned long long wl[4], wr[4];
        #pragma unroll
        for (int jp = 0; jp < 4; jp++) { wl[jp] = wl64[jp]; wr[jp] = wr64[jp]; }

        const float* ab = as_ + n0 * ASTRIDE + k;
        const float* hb = hs_ + n0 * ASTRIDE + k;
        #pragma unroll
        for (int n = 0; n < 8; n++) {
            unsigned long long a2 = pack2(ab[n * ASTRIDE]);
            unsigned long long h2 = pack2(hb[n * ASTRIDE]);
            #pragma unroll
            for (int jp = 0; jp < 4; jp++) {
                ffma2(acc[n][jp], a2, wl[jp]);
                ffma2(acc[n][jp], h2, wr[jp]);
            }
        }
    }

    float bias[8];
    #pragma unroll
    for (int j = 0; j < 8; j++) bias[j] = bl[f0 + j];

    #pragma unroll
    for (int n = 0; n < 8; n++) {
        int gn = base + n0 + n;
        if (gn >= N_NODES) continue;
        float v[8];
        #pragma unroll
        for (int jp = 0; jp < 4; jp++) {
            float2 p = unpack2(acc[n][jp]);
            v[2 * jp]     = p.x + bias[2 * jp];
            v[2 * jp + 1] = p.y + bias[2 * jp + 1];
        }
        if (do_tanh) {
            #pragma unroll
            for (int j = 0; j < 8; j++) v[j] = fast_tanh(v[j]);
        }
        float* op = hout + (size_t)gn * 64 + f0;
        *(float4*)(op)     = make_float4(v[0], v[1], v[2], v[3]);
        *(float4*)(op + 4) = make_float4(v[4], v[5], v[6], v[7]);
    }
}

// ---------------- launch -----------------------------------------------------
extern "C" void kernel_launch(void* const* d_in, const int* in_sizes, int n_in,
                              void* d_out, int out_size) {
    const float* x      = (const float*)d_in[0];
    const void*  ei     = d_in[1];
    const float* Wl_in  = (const float*)d_in[2];
    const float* bl_in  = (const float*)d_in[3];
    const float* Wr_in  = (const float*)d_in[4];
    const float* Wl_med = (const float*)d_in[5];
    const float* bl_med = (const float*)d_in[6];
    const float* Wr_med = (const float*)d_in[7];
    const float* Wl_out = (const float*)d_in[8];
    const float* bl_out = (const float*)d_in[9];
    const float* Wr_out = (const float*)d_in[10];
    float*       out    = (float*)d_out;

    static int smem_set = 0;
    const int LIN_SMEM = LIN_SMEM_FLOATS * 4;   // 100,352 bytes
    if (!smem_set) {
        cudaFuncSetAttribute(lin_kernel,
                             cudaFuncAttributeMaxDynamicSharedMemorySize, LIN_SMEM);
        smem_set = 1;
    }

    // CSR build
    zerodetect_kernel<<<(N_NODES + 255) / 256, 256>>>((const int*)ei);
    count_kernel<<<640, 256>>>(ei);
    part_sum_kernel<<<NPART, SCAN_BLK>>>();
    part_scan_kernel<<<1, 512>>>();
    offsets_kernel<<<NPART, SCAN_BLK>>>();
    fill_kernel<<<640, 256>>>(ei);

    const int AGG_BLOCKS = (N_NODES * 32 + 255) / 256;      // 1 warp / node
    const int LIN_BLOCKS = (N_NODES + TILE_NODES - 1) / TILE_NODES;  // 782

    agg_kernel<<<AGG_BLOCKS, 256>>>(x, -1);
    lin_kernel<<<LIN_BLOCKS, LIN_THREADS, LIN_SMEM>>>(x, -1, 0, nullptr,
                                                      Wl_in, bl_in, Wr_in, 1);
    agg_kernel<<<AGG_BLOCKS, 256>>>(nullptr, 0);
    lin_kernel<<<LIN_BLOCKS, LIN_THREADS, LIN_SMEM>>>(nullptr, 0, 1, nullptr,
                                                      Wl_med, bl_med, Wr_med, 1);
    agg_kernel<<<AGG_BLOCKS, 256>>>(nullptr, 1);
    lin_kernel<<<LIN_BLOCKS, LIN_THREADS, LIN_SMEM>>>(nullptr, 1, 0, nullptr,
                                                      Wl_med, bl_med, Wr_med, 1);
    agg_kernel<<<AGG_BLOCKS, 256>>>(nullptr, 0);
    lin_kernel<<<LIN_BLOCKS, LIN_THREADS, LIN_SMEM>>>(nullptr, 0, -1, out,
                                                      Wl_out, bl_out, Wr_out, 0);
}